// round 3
// baseline (speedup 1.0000x reference)
#include <cuda_runtime.h>

// ConstituencyMFVI: B=32, L=128.
// q[b,i,j] = span[b,i,j] + sum_k pair_m[b,i,j,k] * sigmoid(q[b,i,k]),  3 iterations.
// pair_m[j,k] = pair[j,k] * (mask[b,i,j] && k != min(i,j) && k != max(i,j))
// out = sigmoid(q).
//
// One CTA per (b,i). 128 threads, thread j owns output row element j.
// pair slice (64KB) staged once in SMEM (row pitch 132 floats: conflict-free
// float4 STS and LDS). sigma vector in SMEM, broadcast-read as float4.
//
// NOTE: mask arrives from the harness as a 4-byte-per-element array (bool is
// promoted to int32/float32; only those dtypes exist in the harness contract).
// Read as 32-bit words and test != 0.

#define LL 128
#define LP 132            // padded row pitch in floats
#define N_ITER 3

__global__ __launch_bounds__(LL)
void mfvi_kernel(const float* __restrict__ s_span,
                 const float* __restrict__ s_pair,
                 const unsigned int* __restrict__ mask,
                 float* __restrict__ out)
{
    extern __shared__ float smem[];
    float* sp  = smem;            // [LL][LP] masked pair slice
    float* sig = smem + LL * LP;  // [LL] sigmoid(q)

    const int bi = blockIdx.x;            // b*LL + i
    const int i  = bi & (LL - 1);
    const int t  = threadIdx.x;           // 0..127, thread t owns row j = t

    const float*        pair = s_pair + (size_t)bi * LL * LL;
    const float*        span = s_span + (size_t)bi * LL;
    const unsigned int* mrow = mask   + (size_t)bi * LL;   // 4-byte elements

    // ---- Phase A: coalesced float4 load of the 128x128 slice, masked, into SMEM.
    #pragma unroll 8
    for (int it = 0; it < (LL * LL / 4) / LL; ++it) {   // 32 iterations
        const int f  = t + it * LL;       // float4 index in [0, 4096)
        const int j  = f >> 5;            // 32 float4 per row
        const int k4 = (f & 31) << 2;     // first k of this float4
        float4 v = reinterpret_cast<const float4*>(pair)[f];
        const int  ls  = min(i, j);
        const int  rs  = max(i, j);
        const bool on  = (mrow[j] != 0u);
        v.x = (on && k4 + 0 != ls && k4 + 0 != rs) ? v.x : 0.f;
        v.y = (on && k4 + 1 != ls && k4 + 1 != rs) ? v.y : 0.f;
        v.z = (on && k4 + 2 != ls && k4 + 2 != rs) ? v.z : 0.f;
        v.w = (on && k4 + 3 != ls && k4 + 3 != rs) ? v.w : 0.f;
        reinterpret_cast<float4*>(sp + j * LP)[k4 >> 2] = v;
    }

    // Initial sigma from s_span
    const float myspan = span[t];
    float sv = 1.f / (1.f + expf(-myspan));
    sig[t] = sv;
    __syncthreads();

    const float4* myrow = reinterpret_cast<const float4*>(sp + t * LP);
    const float4* sig4  = reinterpret_cast<const float4*>(sig);

    #pragma unroll 1
    for (int iter = 0; iter < N_ITER; ++iter) {
        float a0 = 0.f, a1 = 0.f, a2 = 0.f, a3 = 0.f;
        #pragma unroll
        for (int m = 0; m < LL / 4; ++m) {
            const float4 p = myrow[m];
            const float4 s = sig4[m];     // broadcast across warp
            a0 += p.x * s.x;
            a1 += p.y * s.y;
            a2 += p.z * s.z;
            a3 += p.w * s.w;
        }
        const float q = myspan + ((a0 + a1) + (a2 + a3));
        sv = 1.f / (1.f + expf(-q));
        __syncthreads();                  // all reads of old sig done
        sig[t] = sv;
        __syncthreads();                  // new sig visible
    }

    out[(size_t)bi * LL + t] = sv;        // coalesced fp32 store
}

extern "C" void kernel_launch(void* const* d_in, const int* in_sizes, int n_in,
                              void* d_out, int out_size) {
    const float*        s_span = (const float*)d_in[0];
    const float*        s_pair = (const float*)d_in[1];
    const unsigned int* mask   = (const unsigned int*)d_in[2];
    float*              out    = (float*)d_out;

    const int B = in_sizes[0] / (LL * LL);        // 32
    const int grid = B * LL;                      // 4096 CTAs, one per (b,i)
    const int smem_bytes = (LL * LP + LL) * (int)sizeof(float);   // ~68 KB

    cudaFuncSetAttribute(mfvi_kernel,
                         cudaFuncAttributeMaxDynamicSharedMemorySize, smem_bytes);

    mfvi_kernel<<<grid, LL, smem_bytes>>>(s_span, s_pair, mask, out);
}

// round 5
// speedup vs baseline: 1.0023x; 1.0023x over previous
#include <cuda_runtime.h>

// ConstituencyMFVI: B=32, L=128.
// q[b,i,j] = span[b,i,j] + sum_k pair_m[b,i,j,k] * sigmoid(q[b,i,k]),  3 iterations.
// pair_m[j,k] = pair[j,k] * (mask[b,i,j] && k != min(i,j) && k != max(i,j))
// out = sigmoid(q).
//
// One CTA per (b,i). 128 threads, thread j owns output row element j.
// pair slice (64KB) staged once in SMEM (row pitch 132 floats: conflict-free
// float4 STS and LDS). sigma vector in SMEM, broadcast-read as float4.
//
// NOTE: mask arrives from the harness as a 4-byte-per-element array (bool is
// promoted to int32/float32; only those dtypes exist in the harness contract).
// Read as 32-bit words and test != 0.

#define LL 128
#define LP 132            // padded row pitch in floats
#define N_ITER 3

__global__ __launch_bounds__(LL)
void mfvi_kernel(const float* __restrict__ s_span,
                 const float* __restrict__ s_pair,
                 const unsigned int* __restrict__ mask,
                 float* __restrict__ out)
{
    extern __shared__ float smem[];
    float* sp  = smem;            // [LL][LP] masked pair slice
    float* sig = smem + LL * LP;  // [LL] sigmoid(q)

    const int bi = blockIdx.x;            // b*LL + i
    const int i  = bi & (LL - 1);
    const int t  = threadIdx.x;           // 0..127, thread t owns row j = t

    const float*        pair = s_pair + (size_t)bi * LL * LL;
    const float*        span = s_span + (size_t)bi * LL;
    const unsigned int* mrow = mask   + (size_t)bi * LL;   // 4-byte elements

    // ---- Phase A: coalesced float4 load of the 128x128 slice, masked, into SMEM.
    #pragma unroll 8
    for (int it = 0; it < (LL * LL / 4) / LL; ++it) {   // 32 iterations
        const int f  = t + it * LL;       // float4 index in [0, 4096)
        const int j  = f >> 5;            // 32 float4 per row
        const int k4 = (f & 31) << 2;     // first k of this float4
        float4 v = reinterpret_cast<const float4*>(pair)[f];
        const int  ls  = min(i, j);
        const int  rs  = max(i, j);
        const bool on  = (mrow[j] != 0u);
        v.x = (on && k4 + 0 != ls && k4 + 0 != rs) ? v.x : 0.f;
        v.y = (on && k4 + 1 != ls && k4 + 1 != rs) ? v.y : 0.f;
        v.z = (on && k4 + 2 != ls && k4 + 2 != rs) ? v.z : 0.f;
        v.w = (on && k4 + 3 != ls && k4 + 3 != rs) ? v.w : 0.f;
        reinterpret_cast<float4*>(sp + j * LP)[k4 >> 2] = v;
    }

    // Initial sigma from s_span
    const float myspan = span[t];
    float sv = 1.f / (1.f + expf(-myspan));
    sig[t] = sv;
    __syncthreads();

    const float4* myrow = reinterpret_cast<const float4*>(sp + t * LP);
    const float4* sig4  = reinterpret_cast<const float4*>(sig);

    #pragma unroll 1
    for (int iter = 0; iter < N_ITER; ++iter) {
        float a0 = 0.f, a1 = 0.f, a2 = 0.f, a3 = 0.f;
        #pragma unroll
        for (int m = 0; m < LL / 4; ++m) {
            const float4 p = myrow[m];
            const float4 s = sig4[m];     // broadcast across warp
            a0 += p.x * s.x;
            a1 += p.y * s.y;
            a2 += p.z * s.z;
            a3 += p.w * s.w;
        }
        const float q = myspan + ((a0 + a1) + (a2 + a3));
        sv = 1.f / (1.f + expf(-q));
        __syncthreads();                  // all reads of old sig done
        sig[t] = sv;
        __syncthreads();                  // new sig visible
    }

    out[(size_t)bi * LL + t] = sv;        // coalesced fp32 store
}

extern "C" void kernel_launch(void* const* d_in, const int* in_sizes, int n_in,
                              void* d_out, int out_size) {
    const float*        s_span = (const float*)d_in[0];
    const float*        s_pair = (const float*)d_in[1];
    const unsigned int* mask   = (const unsigned int*)d_in[2];
    float*              out    = (float*)d_out;

    const int B = in_sizes[0] / (LL * LL);        // 32
    const int grid = B * LL;                      // 4096 CTAs, one per (b,i)
    const int smem_bytes = (LL * LP + LL) * (int)sizeof(float);   // ~68 KB

    cudaFuncSetAttribute(mfvi_kernel,
                         cudaFuncAttributeMaxDynamicSharedMemorySize, smem_bytes);

    mfvi_kernel<<<grid, LL, smem_bytes>>>(s_span, s_pair, mask, out);
}